// round 1
// baseline (speedup 1.0000x reference)
#include <cuda_runtime.h>

// PMSN / S4 convolution-kernel materialization:
//   out[h,l] = Re[ sum_n Ceff[h,n] * exp(Adt[h,n] * l) ],  l = 0..L-1
// where A = -exp(log_A_real) + i*A_imag, Adt = A*dt, A_bar = exp(Adt),
//       B_bar = (A_bar - 1)*B/A, Ceff = C * B_bar.
//
// Strategy: one CTA per h (64 threads). Thread tid owns l = tid + 64*k.
// State P[n] = Ceff[n] * exp(Adt[n]*l) advances by constant complex
// multiplier M[n] = exp(Adt[n]*64) each step -> 4 complex muls + 3 adds
// per output element, all on the FMA pipe. Stores are warp-coalesced
// (32 consecutive floats per warp per step).

#define NSTATE 4
#define BLOCK_T 64

__global__ __launch_bounds__(BLOCK_T)
void pmsn_kernel(const float* __restrict__ log_dt,
                 const float* __restrict__ log_A_real,
                 const float* __restrict__ A_imag,
                 const float* __restrict__ VinvB_r,
                 const float* __restrict__ VinvB_i,
                 const float* __restrict__ CV_r,
                 const float* __restrict__ CV_i,
                 float* __restrict__ out,
                 int L)
{
    const int h   = blockIdx.x;
    const int tid = threadIdx.x;

    const float dt = __expf(log_dt[h]);

    float pr[NSTATE], pi[NSTATE];   // running state P = Ceff * A_bar^l
    float mr[NSTATE], mi[NSTATE];   // stride multiplier M = A_bar^BLOCK_T

    #pragma unroll
    for (int n = 0; n < NSTATE; n++) {
        const int idx = h * NSTATE + n;
        const float ar = -__expf(log_A_real[idx]);
        const float ai = A_imag[idx];
        const float adr = ar * dt;      // Re(Adt)
        const float adi = ai * dt;      // Im(Adt)

        // A_bar = exp(Adt)
        float s1, c1;
        const float ea = __expf(adr);
        __sincosf(adi, &s1, &c1);
        const float abr = ea * c1;
        const float abi = ea * s1;

        // B_bar = (A_bar - 1) * B / A
        const float br = VinvB_r[idx], bi = VinvB_i[idx];
        const float nr = abr - 1.0f, ni = abi;
        const float nb_r = nr * br - ni * bi;
        const float nb_i = nr * bi + ni * br;
        const float inv = 1.0f / (ar * ar + ai * ai);
        const float bb_r = (nb_r * ar + nb_i * ai) * inv;
        const float bb_i = (nb_i * ar - nb_r * ai) * inv;

        // Ceff = C * B_bar
        const float cr = CV_r[idx], ci = CV_i[idx];
        const float ce_r = cr * bb_r - ci * bb_i;
        const float ce_i = cr * bb_i + ci * bb_r;

        // P0 = Ceff * exp(Adt * tid)
        const float ft = (float)tid;
        float s0, c0;
        const float e0 = __expf(adr * ft);
        __sincosf(adi * ft, &s0, &c0);
        const float k0r = e0 * c0;
        const float k0i = e0 * s0;
        pr[n] = ce_r * k0r - ce_i * k0i;
        pi[n] = ce_r * k0i + ce_i * k0r;

        // M = exp(Adt * BLOCK_T)
        const float fs = (float)BLOCK_T;
        float sm, cm;
        const float em = __expf(adr * fs);
        __sincosf(adi * fs, &sm, &cm);
        mr[n] = em * cm;
        mi[n] = em * sm;
    }

    float* o = out + (long long)h * L + tid;
    const int steps = L / BLOCK_T;   // L assumed multiple of BLOCK_T (4096/64)

    #pragma unroll 4
    for (int k = 0; k < steps; k++) {
        const float v = (pr[0] + pr[1]) + (pr[2] + pr[3]);
        o[(long long)k * BLOCK_T] = v;
        #pragma unroll
        for (int n = 0; n < NSTATE; n++) {
            const float t_r = pr[n] * mr[n] - pi[n] * mi[n];
            const float t_i = pr[n] * mi[n] + pi[n] * mr[n];
            pr[n] = t_r;
            pi[n] = t_i;
        }
    }
}

extern "C" void kernel_launch(void* const* d_in, const int* in_sizes, int n_in,
                              void* d_out, int out_size)
{
    const float* log_dt     = (const float*)d_in[0];
    const float* log_A_real = (const float*)d_in[1];
    const float* A_imag     = (const float*)d_in[2];
    const float* VinvB_r    = (const float*)d_in[3];
    const float* VinvB_i    = (const float*)d_in[4];
    const float* CV_r       = (const float*)d_in[5];
    const float* CV_i       = (const float*)d_in[6];
    // d_in[7] is L on device; derive L host-side instead (no sync copies allowed).

    const int H = in_sizes[0];            // 2048
    const int L = out_size / H;           // 4096

    pmsn_kernel<<<H, BLOCK_T>>>(log_dt, log_A_real, A_imag,
                                VinvB_r, VinvB_i, CV_r, CV_i,
                                (float*)d_out, L);
}

// round 2
// speedup vs baseline: 1.1106x; 1.1106x over previous
#include <cuda_runtime.h>
#include <cstdint>

// PMSN / S4 kernel materialization:
//   out[h,l] = Re[ sum_n Ceff[h,n] * exp(Adt[h,n] * l) ]
//
// One CTA per h (64 threads). Each thread owns TWO l-streams:
//   l = tid + 64*k            (k = 0..L/128-1)   -> lane .lo of packed regs
//   l = L/2 + tid + 64*k                          -> lane .hi
// Both streams advance by the same complex multiplier M = exp(Adt*64),
// so state updates use Blackwell packed fma.rn.f32x2 (2 results/instr).

#define NSTATE 4
#define BLOCK_T 64

typedef unsigned long long u64;

#define PACK2(d, lo, hi)   asm("mov.b64 %0, {%1, %2};" : "=l"(d) : "f"(lo), "f"(hi))
#define UNPACK2(lo, hi, s) asm("mov.b64 {%0, %1}, %2;" : "=f"(lo), "=f"(hi) : "l"(s))
#define MUL2(d, a, b)      asm("mul.rn.f32x2 %0, %1, %2;" : "=l"(d) : "l"(a), "l"(b))
#define ADD2(d, a, b)      asm("add.rn.f32x2 %0, %1, %2;" : "=l"(d) : "l"(a), "l"(b))
#define FMA2(d, a, b, c)   asm("fma.rn.f32x2 %0, %1, %2, %3;" : "=l"(d) : "l"(a), "l"(b), "l"(c))

__global__ __launch_bounds__(BLOCK_T)
void pmsn_kernel(const float* __restrict__ log_dt,
                 const float* __restrict__ log_A_real,
                 const float* __restrict__ A_imag,
                 const float* __restrict__ VinvB_r,
                 const float* __restrict__ VinvB_i,
                 const float* __restrict__ CV_r,
                 const float* __restrict__ CV_i,
                 float* __restrict__ out,
                 int L)
{
    const int h    = blockIdx.x;
    const int tid  = threadIdx.x;
    const int half = L >> 1;

    const float dt = __expf(log_dt[h]);

    u64 PR[NSTATE], PI[NSTATE];          // packed state {P(l), P(l+half)}
    u64 MR[NSTATE], MI[NSTATE], NMI[NSTATE];   // broadcast multipliers

    #pragma unroll
    for (int n = 0; n < NSTATE; n++) {
        const int idx = h * NSTATE + n;
        const float ar = -__expf(log_A_real[idx]);
        const float ai = A_imag[idx];
        const float adr = ar * dt;
        const float adi = ai * dt;

        // A_bar = exp(Adt)
        float s1, c1;
        const float ea = __expf(adr);
        __sincosf(adi, &s1, &c1);
        const float abr = ea * c1;
        const float abi = ea * s1;

        // B_bar = (A_bar - 1) * B / A
        const float br = VinvB_r[idx], bi = VinvB_i[idx];
        const float nr = abr - 1.0f, ni = abi;
        const float nb_r = nr * br - ni * bi;
        const float nb_i = nr * bi + ni * br;
        const float inv = 1.0f / (ar * ar + ai * ai);
        const float bb_r = (nb_r * ar + nb_i * ai) * inv;
        const float bb_i = (nb_i * ar - nb_r * ai) * inv;

        // Ceff = C * B_bar
        const float cr = CV_r[idx], ci = CV_i[idx];
        const float ce_r = cr * bb_r - ci * bb_i;
        const float ce_i = cr * bb_i + ci * bb_r;

        // P0 at l = tid  (lane lo)
        float sa, ca;
        const float fa = (float)tid;
        const float e0 = __expf(adr * fa);
        __sincosf(adi * fa, &sa, &ca);
        const float k0r = e0 * ca, k0i = e0 * sa;
        const float par = ce_r * k0r - ce_i * k0i;
        const float pai = ce_r * k0i + ce_i * k0r;

        // P0 at l = half + tid  (lane hi)
        float sb, cb;
        const float fb = (float)(half + tid);
        const float e1 = __expf(adr * fb);
        __sincosf(adi * fb, &sb, &cb);
        const float k1r = e1 * cb, k1i = e1 * sb;
        const float pbr = ce_r * k1r - ce_i * k1i;
        const float pbi = ce_r * k1i + ce_i * k1r;

        PACK2(PR[n], par, pbr);
        PACK2(PI[n], pai, pbi);

        // step multiplier M = exp(Adt * BLOCK_T), broadcast to both lanes
        float sm, cm;
        const float fs = (float)BLOCK_T;
        const float em = __expf(adr * fs);
        __sincosf(adi * fs, &sm, &cm);
        const float mr = em * cm, mi = em * sm;
        PACK2(MR[n],  mr,  mr);
        PACK2(MI[n],  mi,  mi);
        PACK2(NMI[n], -mi, -mi);
    }

    float* oa = out + (long long)h * L + tid;
    float* ob = oa + half;
    const int steps = half / BLOCK_T;    // 4096/2/64 = 32

    #pragma unroll 8
    for (int k = 0; k < steps; k++) {
        // v = Re(sum_n P[n]) for both lanes
        u64 s0, s1, s;
        ADD2(s0, PR[0], PR[1]);
        ADD2(s1, PR[2], PR[3]);
        ADD2(s,  s0,    s1);
        float va, vb;
        UNPACK2(va, vb, s);
        oa[k * BLOCK_T] = va;
        ob[k * BLOCK_T] = vb;

        // P *= M (packed complex multiply, both lanes)
        #pragma unroll
        for (int n = 0; n < NSTATE; n++) {
            u64 m1, m2, tr, ti;
            MUL2(m1, PR[n], MR[n]);
            FMA2(tr, PI[n], NMI[n], m1);
            MUL2(m2, PR[n], MI[n]);
            FMA2(ti, PI[n], MR[n], m2);
            PR[n] = tr;
            PI[n] = ti;
        }
    }
}

extern "C" void kernel_launch(void* const* d_in, const int* in_sizes, int n_in,
                              void* d_out, int out_size)
{
    const float* log_dt     = (const float*)d_in[0];
    const float* log_A_real = (const float*)d_in[1];
    const float* A_imag     = (const float*)d_in[2];
    const float* VinvB_r    = (const float*)d_in[3];
    const float* VinvB_i    = (const float*)d_in[4];
    const float* CV_r       = (const float*)d_in[5];
    const float* CV_i       = (const float*)d_in[6];

    const int H = in_sizes[0];            // 2048
    const int L = out_size / H;           // 4096

    pmsn_kernel<<<H, BLOCK_T>>>(log_dt, log_A_real, A_imag,
                                VinvB_r, VinvB_i, CV_r, CV_i,
                                (float*)d_out, L);
}